// round 4
// baseline (speedup 1.0000x reference)
#include <cuda_runtime.h>
#include <cuda_bf16.h>
#include <math.h>

#define NN 50000
#define EE 800000
#define FF 500
#define SW 576        // per-node state: 512 (M = Kf x V) + 64 (Kf)
#define SW4 144       // state width in float4
#define CSTV 1e-5f

// ---------------- static device scratch (no runtime allocation) ----------------
__device__ __align__(16) float g_x[(size_t)NN * 64];
__device__ __align__(16) float g_Q[(size_t)NN * 64];
__device__ __align__(16) float g_V[(size_t)NN * 32];
__device__ __align__(16) float g_s0[(size_t)NN * SW];
__device__ __align__(16) float g_s1[(size_t)NN * SW];
__device__ __align__(16) float g_hidden[(size_t)NN * 32];
__device__ int   g_deg[NN];
__device__ float g_dinv[NN];
__device__ int   g_off[NN + 1];
__device__ int   g_cnt[NN];
__device__ int   g_srcv[EE];
__device__ float g_escale[EE];
__device__ float g_tele[SW];     // teleport sums: 512 of M, 64 of Kf
__device__ int   g_is64;         // edge_index dtype flag (1 = int64, 0 = int32)

// ---------------- K-1: detect edge_index dtype ----------------
// If the first 1024 values interpreted as int64 all lie in [0, NN), the data is
// int64 (for int32 data this would require every odd 32-bit word to be zero).
// Only samples the first EE elements' worth of bytes, safe for either dtype.
__global__ void k_detect(const void* __restrict__ ei) {
    if (blockIdx.x == 0 && threadIdx.x == 0) {
        const long long* p = (const long long*)ei;
        int ok = 1;
        for (int i = 0; i < 1024; i++) {
            long long v = p[i];
            if (v < 0 || v >= NN) { ok = 0; break; }
        }
        g_is64 = ok;
    }
}

__device__ __forceinline__ int edge_at(const void* __restrict__ ei, int half, int e, int is64) {
    if (is64) return (int)((const long long*)ei)[(size_t)half * EE + e];
    return ((const int*)ei)[(size_t)half * EE + e];
}

// ---------------- K0: zero counters ----------------
__global__ void k_zero() {
    int i = blockIdx.x * blockDim.x + threadIdx.x;
    if (i < NN) { g_deg[i] = 0; g_cnt[i] = 0; }
    if (i < SW) g_tele[i] = 0.f;
}

// ---------------- K1: in-degree over col ----------------
__global__ void k_deg(const void* __restrict__ ei) {
    int e = blockIdx.x * blockDim.x + threadIdx.x;
    int is64 = g_is64;
    if (e < EE) {
        int c = edge_at(ei, 1, e, is64);
        atomicAdd(&g_deg[c], 1);
    }
}

// ---------------- K2: deg^-1 ----------------
__global__ void k_dinv() {
    int i = blockIdx.x * blockDim.x + threadIdx.x;
    if (i < NN) {
        int d = g_deg[i];
        g_dinv[i] = d > 0 ? 1.f / (float)d : 0.f;
    }
}

// ---------------- K3: exclusive scan of deg -> CSR offsets (single block) ----------------
__global__ void k_scan() {
    __shared__ int s[1024];
    int tid = threadIdx.x;
    const int CH = (NN + 1023) / 1024;   // 49
    int st = tid * CH;
    int en = st + CH; if (en > NN) en = NN;
    int sum = 0;
    for (int i = st; i < en; i++) sum += g_deg[i];
    s[tid] = sum;
    __syncthreads();
    for (int d = 1; d < 1024; d <<= 1) {
        int v = 0;
        if (tid >= d) v = s[tid - d];
        __syncthreads();
        if (tid >= d) s[tid] += v;
        __syncthreads();
    }
    int run = (tid > 0) ? s[tid - 1] : 0;
    for (int i = st; i < en; i++) { g_off[i] = run; run += g_deg[i]; }
    if (tid == 1023) g_off[NN] = s[1023];
}

// ---------------- K4: fill CSR (grouped by destination) + per-edge scale ----------------
__global__ void k_fill(const void* __restrict__ ei) {
    int e = blockIdx.x * blockDim.x + threadIdx.x;
    int is64 = g_is64;
    if (e < EE) {
        int c = edge_at(ei, 1, e, is64);
        int r = edge_at(ei, 0, e, is64);
        int pos = g_off[c] + atomicAdd(&g_cnt[c], 1);
        g_srcv[pos] = r;
        g_escale[pos] = g_dinv[r];   // norm = deg_inv[row[e]]
    }
}

// ---------------- K5: x = relu(node_feat @ Wi + bi)   [N,500]x[500,64] ----------------
__global__ void __launch_bounds__(256) k_gemm1(const float* __restrict__ A,
                                               const float* __restrict__ Wi,
                                               const float* __restrict__ bi) {
    __shared__ float As[64][33];
    __shared__ __align__(16) float Bs[32 * 64];
    int tid = threadIdx.x;
    int row0 = blockIdx.x * 64;
    int tc = tid & 15;    // 0..15 -> 4 cols each
    int tr = tid >> 4;    // 0..15 -> 4 rows each
    float acc[4][4];
    #pragma unroll
    for (int i = 0; i < 4; i++)
        #pragma unroll
        for (int j = 0; j < 4; j++) acc[i][j] = 0.f;

    for (int k0 = 0; k0 < FF; k0 += 32) {
        #pragma unroll
        for (int it = 0; it < 8; it++) {
            int idx = tid + it * 256;
            int r = idx >> 5, kk = idx & 31;
            int gr = row0 + r, gk = k0 + kk;
            As[r][kk] = (gr < NN && gk < FF) ? A[(size_t)gr * FF + gk] : 0.f;
        }
        #pragma unroll
        for (int it = 0; it < 8; it++) {
            int idx = tid + it * 256;
            int kk = idx >> 6, c = idx & 63;
            int gk = k0 + kk;
            Bs[idx] = (gk < FF) ? Wi[gk * 64 + c] : 0.f;
        }
        __syncthreads();
        #pragma unroll
        for (int kk = 0; kk < 32; kk++) {
            float a[4];
            #pragma unroll
            for (int i = 0; i < 4; i++) a[i] = As[tr * 4 + i][kk];
            float4 bv = *(const float4*)&Bs[kk * 64 + tc * 4];
            float b[4] = {bv.x, bv.y, bv.z, bv.w};
            #pragma unroll
            for (int i = 0; i < 4; i++)
                #pragma unroll
                for (int j = 0; j < 4; j++)
                    acc[i][j] = fmaf(a[i], b[j], acc[i][j]);
        }
        __syncthreads();
    }
    #pragma unroll
    for (int i = 0; i < 4; i++) {
        int r = row0 + tr * 4 + i;
        if (r < NN) {
            #pragma unroll
            for (int j = 0; j < 4; j++) {
                int c = tc * 4 + j;
                float v = acc[i][j] + bi[c];
                g_x[(size_t)r * 64 + c] = v > 0.f ? v : 0.f;
            }
        }
    }
}

// ---------------- K6: fused QKV projections  [N,64]x[64,160] ----------------
// cols 0..63 -> Q (1+elu), 64..127 -> Kf (1+elu, stored in state tail), 128..159 -> V
__global__ void __launch_bounds__(256) k_gemm2(const float* __restrict__ Wq, const float* __restrict__ bq,
                                               const float* __restrict__ Wk, const float* __restrict__ bk,
                                               const float* __restrict__ Wv, const float* __restrict__ bv) {
    __shared__ float Xs[64][33];
    __shared__ float Ws[32][160];
    int tid = threadIdx.x;
    int row0 = blockIdx.x * 64;
    int tc = tid & 15;    // 10 cols each
    int tr = tid >> 4;    // 4 rows each
    float acc[4][10];
    #pragma unroll
    for (int i = 0; i < 4; i++)
        #pragma unroll
        for (int j = 0; j < 10; j++) acc[i][j] = 0.f;

    for (int kt = 0; kt < 2; kt++) {
        #pragma unroll
        for (int it = 0; it < 8; it++) {
            int idx = tid + it * 256;
            int r = idx >> 5, kk = idx & 31;
            int gr = row0 + r;
            Xs[r][kk] = (gr < NN) ? g_x[(size_t)gr * 64 + kt * 32 + kk] : 0.f;
        }
        #pragma unroll
        for (int it = 0; it < 20; it++) {
            int idx = tid + it * 256;
            int kk = idx / 160, c = idx % 160;
            int gk = kt * 32 + kk;
            float w;
            if (c < 64)       w = Wq[gk * 64 + c];
            else if (c < 128) w = Wk[gk * 64 + (c - 64)];
            else              w = Wv[gk * 32 + (c - 128)];
            Ws[kk][c] = w;
        }
        __syncthreads();
        #pragma unroll
        for (int kk = 0; kk < 32; kk++) {
            float a[4];
            #pragma unroll
            for (int i = 0; i < 4; i++) a[i] = Xs[tr * 4 + i][kk];
            float b[10];
            #pragma unroll
            for (int j = 0; j < 10; j++) b[j] = Ws[kk][tc * 10 + j];
            #pragma unroll
            for (int i = 0; i < 4; i++)
                #pragma unroll
                for (int j = 0; j < 10; j++)
                    acc[i][j] = fmaf(a[i], b[j], acc[i][j]);
        }
        __syncthreads();
    }

    #pragma unroll
    for (int i = 0; i < 4; i++) {
        int r = row0 + tr * 4 + i;
        if (r >= NN) continue;
        #pragma unroll
        for (int j = 0; j < 10; j++) {
            int c = tc * 10 + j;
            float v = acc[i][j];
            if (c < 64) {
                v += bq[c];
                v = v > 0.f ? 1.f + v : expf(v);   // 1 + elu
                g_Q[(size_t)r * 64 + c] = v;
            } else if (c < 128) {
                int cc = c - 64;
                v += bk[cc];
                v = v > 0.f ? 1.f + v : expf(v);
                g_s0[(size_t)r * SW + 512 + cc] = v;
            } else {
                int cc = c - 128;
                v += bv[cc];
                g_V[(size_t)r * 32 + cc] = v;
            }
        }
    }
}

// ---------------- K7: M0 = Kf (x) V, hidden init, teleport partial sums ----------------
// state[n][t]:  t<512 -> M[h][i][j] at h*128+i*8+j ; t>=512 -> Kf[h*16+i]
__global__ void __launch_bounds__(576) k_build(const float* __restrict__ hopwise) {
    __shared__ float skf[64], sv[32];
    int t = threadIdx.x;
    int n0 = blockIdx.x * 32;
    float tele = 0.f;
    float hop0 = hopwise[0];
    for (int nn = 0; nn < 32; nn++) {
        int n = n0 + nn;
        if (n >= NN) break;          // uniform across block
        __syncthreads();
        if (t < 64)      skf[t]     = g_s0[(size_t)n * SW + 512 + t];
        else if (t < 96) sv[t - 64] = g_V[(size_t)n * 32 + (t - 64)];
        __syncthreads();
        if (t < 512) {
            float m = skf[t >> 3] * sv[((t >> 7) << 3) | (t & 7)];
            g_s0[(size_t)n * SW + t] = m;
            tele += m;
            if (t < 32) g_hidden[(size_t)n * 32 + t] = hop0 * sv[t];
        } else {
            tele += skf[t - 512];
        }
    }
    atomicAdd(&g_tele[t], tele);
}

// ---------------- K8: SpMM hop (CSR gather, fused M|Kf propagation) ----------------
__global__ void __launch_bounds__(160) k_spmm(int dir) {
    const float4* __restrict__ sin = dir ? (const float4*)g_s1 : (const float4*)g_s0;
    float4*       __restrict__ sout = dir ? (float4*)g_s0      : (float4*)g_s1;
    int node = blockIdx.x;
    int t = threadIdx.x;
    if (t >= SW4) return;
    int e = g_off[node];
    int end = g_off[node + 1];
    float4 acc = make_float4(0.f, 0.f, 0.f, 0.f);
    for (; e + 1 < end; e += 2) {
        int   s0i = __ldg(&g_srcv[e]);
        int   s1i = __ldg(&g_srcv[e + 1]);
        float c0  = __ldg(&g_escale[e]);
        float c1  = __ldg(&g_escale[e + 1]);
        float4 v0 = __ldg(&sin[(size_t)s0i * SW4 + t]);
        float4 v1 = __ldg(&sin[(size_t)s1i * SW4 + t]);
        acc.x = fmaf(c0, v0.x, fmaf(c1, v1.x, acc.x));
        acc.y = fmaf(c0, v0.y, fmaf(c1, v1.y, acc.y));
        acc.z = fmaf(c0, v0.z, fmaf(c1, v1.z, acc.z));
        acc.w = fmaf(c0, v0.w, fmaf(c1, v1.w, acc.w));
    }
    if (e < end) {
        int   si = __ldg(&g_srcv[e]);
        float c  = __ldg(&g_escale[e]);
        float4 v = __ldg(&sin[(size_t)si * SW4 + t]);
        acc.x = fmaf(c, v.x, acc.x);
        acc.y = fmaf(c, v.y, acc.y);
        acc.z = fmaf(c, v.z, acc.z);
        acc.w = fmaf(c, v.w, acc.w);
    }
    sout[(size_t)node * SW4 + t] = acc;
}

// ---------------- K9: per-hop attention contraction -> hidden ----------------
// thread = (node_local, h, j); 8 nodes per 256-thread block
__global__ void __launch_bounds__(256) k_att(int dir, int hop,
                                             const float* __restrict__ hopwise,
                                             const float* __restrict__ headwise) {
    const float* __restrict__ st = dir ? g_s0 : g_s1;   // dir: which buffer holds hop result
    __shared__ float sQ[8][64];
    __shared__ float sgamma[4];
    int tid = threadIdx.x;
    int n0 = blockIdx.x * 8;

    // gamma[h] = hopwise[hop+1] * softmax_h(headwise[:,hop])[h]
    if (tid < 4) {
        float w0 = headwise[0 * 2 + hop], w1 = headwise[1 * 2 + hop];
        float w2 = headwise[2 * 2 + hop], w3 = headwise[3 * 2 + hop];
        float mx = fmaxf(fmaxf(w0, w1), fmaxf(w2, w3));
        float e0 = expf(w0 - mx), e1 = expf(w1 - mx), e2 = expf(w2 - mx), e3 = expf(w3 - mx);
        float inv = 1.f / (e0 + e1 + e2 + e3);
        float me = (tid == 0) ? e0 : (tid == 1) ? e1 : (tid == 2) ? e2 : e3;
        sgamma[tid] = hopwise[hop + 1] * me * inv;
    }
    #pragma unroll
    for (int it = 0; it < 2; it++) {
        int idx = tid + it * 256;
        int nl = idx >> 6, k = idx & 63;
        int n = n0 + nl;
        sQ[nl][k] = (n < NN) ? g_Q[(size_t)n * 64 + k] : 0.f;
    }
    __syncthreads();

    int nl = tid >> 5;
    int lane = tid & 31;
    int h = lane >> 3, j = lane & 7;
    int n = n0 + nl;
    if (n >= NN) return;

    const float* srow = st + (size_t)n * SW;
    float hh = 0.f, cc = CSTV;
    #pragma unroll
    for (int i = 0; i < 16; i++) {
        float q = sQ[nl][h * 16 + i];
        hh = fmaf(q, __ldg(&srow[h * 128 + i * 8 + j]), hh);
        cc = fmaf(q, __ldg(&srow[512 + h * 16 + i]), cc);
    }
    g_hidden[(size_t)n * 32 + h * 8 + j] += sgamma[h] * hh / cc;
}

// ---------------- K10: output projection + teleport term ----------------
__global__ void __launch_bounds__(256) k_out(const float* __restrict__ Wo,
                                             const float* __restrict__ bo,
                                             const float* __restrict__ teleport,
                                             float* __restrict__ out) {
    __shared__ float sTele[SW];        // g_tele / N
    __shared__ float sWo[32 * 8];
    __shared__ float sQ[32][64];
    __shared__ float sH[32][32];
    int tid = threadIdx.x;
    int n0 = blockIdx.x * 32;

    #pragma unroll
    for (int it = 0; it < 3; it++) {
        int idx = tid + it * 256;
        if (idx < SW) sTele[idx] = g_tele[idx] * (1.f / (float)NN);
    }
    if (tid < 32 * 8) sWo[tid] = Wo[tid];
    #pragma unroll
    for (int it = 0; it < 8; it++) {
        int idx = tid + it * 256;
        int nl = idx >> 6, k = idx & 63;
        int n = n0 + nl;
        sQ[nl][k] = (n < NN) ? g_Q[(size_t)n * 64 + k] : 0.f;
    }
    #pragma unroll
    for (int it = 0; it < 4; it++) {
        int idx = tid + it * 256;
        int nl = idx >> 5, k = idx & 31;
        int n = n0 + nl;
        sH[nl][k] = (n < NN) ? g_hidden[(size_t)n * 32 + k] : 0.f;
    }
    __syncthreads();

    int nl = tid >> 3;
    int c = tid & 7;
    int n = n0 + nl;
    if (n >= NN) return;

    // output projection
    float acc = bo[c];
    #pragma unroll
    for (int hc = 0; hc < 32; hc++)
        acc = fmaf(sH[nl][hc], sWo[hc * 8 + c], acc);

    // teleport term: sum_h (Q . teleM[:, c]) / (Q . teleK + CST)
    float tsum = 0.f;
    #pragma unroll
    for (int h = 0; h < 4; h++) {
        float num = 0.f, den = CSTV;
        #pragma unroll
        for (int i = 0; i < 16; i++) {
            float q = sQ[nl][h * 16 + i];
            num = fmaf(q, sTele[h * 128 + i * 8 + c], num);
            den = fmaf(q, sTele[512 + h * 16 + i], den);
        }
        tsum += num / den;
    }
    out[(size_t)n * 8 + c] = acc + teleport[0] * tsum;
}

// ---------------- launch ----------------
extern "C" void kernel_launch(void* const* d_in, const int* in_sizes, int n_in,
                              void* d_out, int out_size) {
    const float* nf  = (const float*)d_in[0];
    const void*  ei  = d_in[1];                 // int32 or int64, detected on device
    const float* Wi  = (const float*)d_in[2];
    const float* bi  = (const float*)d_in[3];
    const float* Wq  = (const float*)d_in[4];
    const float* bq  = (const float*)d_in[5];
    const float* Wk  = (const float*)d_in[6];
    const float* bk  = (const float*)d_in[7];
    const float* Wv  = (const float*)d_in[8];
    const float* bv  = (const float*)d_in[9];
    const float* Wo  = (const float*)d_in[10];
    const float* bo  = (const float*)d_in[11];
    const float* hw  = (const float*)d_in[12];
    const float* hdw = (const float*)d_in[13];
    const float* tp  = (const float*)d_in[14];
    float* out = (float*)d_out;

    k_detect<<<1, 32>>>(ei);
    k_zero<<<(NN + 255) / 256, 256>>>();
    k_deg<<<(EE + 255) / 256, 256>>>(ei);
    k_dinv<<<(NN + 255) / 256, 256>>>();
    k_scan<<<1, 1024>>>();
    k_fill<<<(EE + 255) / 256, 256>>>(ei);

    k_gemm1<<<(NN + 63) / 64, 256>>>(nf, Wi, bi);
    k_gemm2<<<(NN + 63) / 64, 256>>>(Wq, bq, Wk, bk, Wv, bv);
    k_build<<<(NN + 31) / 32, 576>>>(hw);

    // hop 0: s0 -> s1
    k_spmm<<<NN, 160>>>(0);
    k_att<<<(NN + 7) / 8, 256>>>(0, 0, hw, hdw);
    // hop 1: s1 -> s0
    k_spmm<<<NN, 160>>>(1);
    k_att<<<(NN + 7) / 8, 256>>>(1, 1, hw, hdw);

    k_out<<<(NN + 31) / 32, 256>>>(Wo, bo, tp, out);
}